// round 11
// baseline (speedup 1.0000x reference)
#include <cuda_runtime.h>
#include <cuda_fp16.h>
#include <math.h>
#include <stdint.h>

#define NH 6
#define NB 512
#define ND 2048
#define NC 1000
#define NP 1024
#define TAU 0.5f

#define BK 32
#define NITER (ND / BK)          // 64
#define STAGES 3
#define STG_BYTES (12 * 1024)    // Ah 4K | Bh 8K
#define GSMEM (STAGES * STG_BYTES)

// ------------------------- scratch ------------------------------------------
__device__ __half g_Ah[NH * NB * ND];
__device__ __half g_Bh[NH * NP * ND];   // [h][n][k]
__device__ float g_logits[NH * NB * NC];

// ------------------------- helpers ------------------------------------------
__device__ __forceinline__ uint32_t smem_u32(const void* p) {
    uint32_t a;
    asm("{ .reg .u64 t; cvta.to.shared.u64 t, %1; cvt.u32.u64 %0, t; }" : "=r"(a) : "l"(p));
    return a;
}
__device__ __forceinline__ void cp16(uint32_t dst, const void* src) {
    asm volatile("cp.async.cg.shared.global [%0], [%1], 16;\n" :: "r"(dst), "l"(src) : "memory");
}
__device__ __forceinline__ void cp_commit() {
    asm volatile("cp.async.commit_group;\n" ::: "memory");
}
template<int N> __device__ __forceinline__ void cp_wait() {
    asm volatile("cp.async.wait_group %0;\n" :: "n"(N) : "memory");
}
__device__ __forceinline__ uint32_t swz_addr(uint32_t base, int row, int colb) {
    return base + (uint32_t)(row * 64 + (colb ^ ((row & 6) << 3)));
}
#define LDSM4(r, a) \
    asm volatile("ldmatrix.sync.aligned.m8n8.x4.shared.b16 {%0,%1,%2,%3}, [%4];" \
        : "=r"((r)[0]), "=r"((r)[1]), "=r"((r)[2]), "=r"((r)[3]) : "r"(a))
#define MMA16816(c, a, b0, b1) \
    asm volatile("mma.sync.aligned.m16n8k16.row.col.f32.f16.f16.f32 " \
        "{%0,%1,%2,%3}, {%4,%5,%6,%7}, {%8,%9}, {%0,%1,%2,%3};" \
        : "+f"((c)[0]), "+f"((c)[1]), "+f"((c)[2]), "+f"((c)[3]) \
        : "r"((a)[0]), "r"((a)[1]), "r"((a)[2]), "r"((a)[3]), "r"(b0), "r"(b1))

// ------------------------- merged conversion kernel --------------------------
#define NA_BLK (NH * NB * ND / 4 / 256)      // 6144

__global__ __launch_bounds__(256) void conv_all(const float* __restrict__ x,
                                                const float* __restrict__ W,
                                                float* __restrict__ out) {
    const int tid = threadIdx.x;
    if (blockIdx.x < NA_BLK) {
        const int i = blockIdx.x * 256 + tid;
        float4 v = ((const float4*)x)[i];
        __half2* ph = (__half2*)g_Ah;
        ph[2*i]   = __halves2half2(__float2half_rn(v.x), __float2half_rn(v.y));
        ph[2*i+1] = __halves2half2(__float2half_rn(v.z), __float2half_rn(v.w));
        return;
    }
    // B role: W [h][k][n] fp32 -> g_Bh [h][n(1024)][k] fp16
    __shared__ float t[32][33];
    const int bi = blockIdx.x - NA_BLK;
    if (bi == 0 && tid == 0) {           // zero the atomic accumulator slots
        out[(size_t)NB * NC + NB + 0] = 0.f;
        out[(size_t)NB * NC + NB + 1] = 0.f;
    }
    const int n0 = (bi & 31) * 32;
    const int k0 = ((bi >> 5) & 63) * 32;
    const int h  = bi >> 11;

    const int tx = tid & 31, ty = tid >> 5;
    #pragma unroll
    for (int i = 0; i < 4; i++) {
        int k = k0 + ty + 8 * i;
        int n = n0 + tx;
        t[ty + 8 * i][tx] = (n < NC) ? W[((size_t)h * ND + k) * NC + n] : 0.f;
    }
    __syncthreads();

    if (tid < 128) {
        const int nn = tid >> 2;
        const int kg = tid & 3;
        __half vals[8];
        #pragma unroll
        for (int j = 0; j < 8; j++)
            vals[j] = __float2half_rn(t[kg * 8 + j][nn]);
        __half* dst = g_Bh + ((size_t)h * NP + n0 + nn) * ND + k0 + kg * 8;
        *(uint4*)dst = *(uint4*)vals;
    }
}

// ------------------------- mma.sync GEMM (unchanged from R10) ----------------
__global__ void __launch_bounds__(128, 4) gemm_mma(const float* __restrict__ bias) {
    extern __shared__ char sm[];
    const uint32_t sb = smem_u32(sm);
    const int tid = threadIdx.x;
    const int wid = tid >> 5, l = tid & 31;
    const int h  = blockIdx.z;
    const int m0 = blockIdx.y * 64;
    const int n0 = blockIdx.x * 128;

    const __half* Ah = g_Ah + ((size_t)h * NB + m0) * ND;
    const __half* Bh = g_Bh + ((size_t)h * NP + n0) * ND;

    auto load_stage = [&](int s, int kt) {
        const uint32_t base = sb + (uint32_t)s * STG_BYTES;
        #pragma unroll
        for (int q6 = 0; q6 < 6; q6++) {
            const int q = tid + q6 * 128;
            const int r  = q >> 2;
            const int ch = q & 3;
            const __half* gp;
            uint32_t reg_off;
            int rr;
            if (r < 64) { gp = Ah + (size_t)r * ND;        reg_off = 0;     rr = r; }
            else        { gp = Bh + (size_t)(r - 64) * ND; reg_off = 4096u; rr = r - 64; }
            cp16(swz_addr(base + reg_off, rr, ch * 16), gp + kt + ch * 8);
        }
        cp_commit();
    };

    load_stage(0, 0);
    load_stage(1, BK);

    const int wn = wid * 32;

    float acc[4][4][4];
    #pragma unroll
    for (int a = 0; a < 4; a++)
        #pragma unroll
        for (int b = 0; b < 4; b++)
            #pragma unroll
            for (int c = 0; c < 4; c++) acc[a][b][c] = 0.f;

    const int lrow = l & 15;
    const int lcb  = (l >> 4) << 4;

    for (int it = 0; it < NITER; it++) {
        if (it + 2 < NITER) cp_wait<1>(); else cp_wait<0>();
        __syncthreads();

        if (it + 2 < NITER) load_stage((it + 2) % STAGES, (it + 2) * BK);

        const uint32_t base  = sb + (uint32_t)(it % STAGES) * STG_BYTES;
        const uint32_t abase = base;
        const uint32_t bbase = base + 4096u;

        #pragma unroll
        for (int kg = 0; kg < 2; kg++) {
            const int cb = kg * 32 + lcb;
            uint32_t bh_[2][4];
            uint32_t ah_[4][4];
            #pragma unroll
            for (int nt = 0; nt < 2; nt++) {
                const int row = wn + nt * 16 + lrow;
                LDSM4(bh_[nt], swz_addr(bbase, row, cb));
            }
            #pragma unroll
            for (int mt = 0; mt < 4; mt++) {
                const int row = mt * 16 + lrow;
                LDSM4(ah_[mt], swz_addr(abase, row, cb));
            }
            #pragma unroll
            for (int mt = 0; mt < 4; mt++)
                #pragma unroll
                for (int nt = 0; nt < 2; nt++)
                    #pragma unroll
                    for (int hf = 0; hf < 2; hf++)
                        MMA16816(acc[mt][nt * 2 + hf], ah_[mt], bh_[nt][hf], bh_[nt][hf + 2]);
        }
        __syncthreads();
    }

    float bs0[4], bs1[4];
    #pragma unroll
    for (int n8 = 0; n8 < 4; n8++) {
        const int c0 = n0 + wn + n8 * 8 + (l & 3) * 2;
        bs0[n8] = (c0 < NC)     ? bias[h * NC + c0]     : 0.f;
        bs1[n8] = (c0 + 1 < NC) ? bias[h * NC + c0 + 1] : 0.f;
    }
    #pragma unroll
    for (int mt = 0; mt < 4; mt++) {
        const int r0 = m0 + mt * 16 + (l >> 2);
        #pragma unroll
        for (int n8 = 0; n8 < 4; n8++) {
            const int c0 = n0 + wn + n8 * 8 + (l & 3) * 2;
            if (c0 < NC) {
                float2 v0 = make_float2(acc[mt][n8][0] + bs0[n8], acc[mt][n8][1] + bs1[n8]);
                float2 v1 = make_float2(acc[mt][n8][2] + bs0[n8], acc[mt][n8][3] + bs1[n8]);
                *(float2*)&g_logits[((size_t)h * NB + r0) * NC + c0]     = v0;
                *(float2*)&g_logits[((size_t)h * NB + r0 + 8) * NC + c0] = v1;
            }
        }
    }
}

// ------------------------- fused post-processing -----------------------------
// One block per sample b: softmax stats for all 6 heads (rows kept in regs),
// routing, output gather from regs, loss/acc via atomicAdd.
__global__ __launch_bounds__(256) void post_k(const int* __restrict__ y_true,
                                              float* __restrict__ out) {
    const int b = blockIdx.x;
    const int tid = threadIdx.x;
    const int w = tid >> 5, lane = tid & 31;

    __shared__ float swv[8];
    __shared__ int   swi[8];
    __shared__ float sws[8];
    __shared__ float s_conf[NH], s_logZ[NH];
    __shared__ int   s_amax[NH];

    float4 v[NH];
    #pragma unroll
    for (int h = 0; h < NH; h++) {
        v[h] = (tid < NC / 4)
             ? ((const float4*)(g_logits + ((size_t)h * NB + b) * NC))[tid]
             : make_float4(-1e30f, -1e30f, -1e30f, -1e30f);
    }

    #pragma unroll
    for (int h = 0; h < NH; h++) {
        float4 x = v[h];
        float vmax = x.x; int imax = tid * 4;
        if (x.y > vmax) { vmax = x.y; imax = tid * 4 + 1; }
        if (x.z > vmax) { vmax = x.z; imax = tid * 4 + 2; }
        if (x.w > vmax) { vmax = x.w; imax = tid * 4 + 3; }
        #pragma unroll
        for (int off = 16; off > 0; off >>= 1) {
            float ov = __shfl_down_sync(0xffffffffu, vmax, off);
            int   oi = __shfl_down_sync(0xffffffffu, imax, off);
            if (ov > vmax || (ov == vmax && oi < imax)) { vmax = ov; imax = oi; }
        }
        if (lane == 0) { swv[w] = vmax; swi[w] = imax; }
        __syncthreads();
        if (tid < 8) {
            vmax = swv[tid]; imax = swi[tid];
            #pragma unroll
            for (int off = 4; off > 0; off >>= 1) {
                float ov = __shfl_down_sync(0xffu, vmax, off);
                int   oi = __shfl_down_sync(0xffu, imax, off);
                if (ov > vmax || (ov == vmax && oi < imax)) { vmax = ov; imax = oi; }
            }
            if (tid == 0) { swv[0] = vmax; swi[0] = imax; }
        }
        __syncthreads();
        const float m = swv[0];
        const int  am = swi[0];

        float sum = __expf(x.x - m) + __expf(x.y - m) + __expf(x.z - m) + __expf(x.w - m);
        #pragma unroll
        for (int off = 16; off > 0; off >>= 1)
            sum += __shfl_down_sync(0xffffffffu, sum, off);
        if (lane == 0) sws[w] = sum;
        __syncthreads();
        if (tid == 0) {
            float s = 0.f;
            #pragma unroll
            for (int i = 0; i < 8; i++) s += sws[i];
            s_conf[h] = 1.f / s;
            s_logZ[h] = m + logf(s);
            s_amax[h] = am;
        }
        __syncthreads();      // also protects swv/swi/sws reuse next head
    }

    // routing (all threads, from smem)
    int fh = -1, bh = 0;
    float bc = -1.f;
    #pragma unroll
    for (int hh = 0; hh < NH; hh++) {
        float cv = s_conf[hh];
        if (fh < 0 && cv >= TAU) fh = hh;
        if (cv > bc) { bc = cv; bh = hh; }
    }
    const int e = (fh >= 0) ? fh : bh;

    // gather chosen row from registers (predicated select, no spill)
    float4 ov = v[0];
    #pragma unroll
    for (int h = 1; h < NH; h++) if (h == e) ov = v[h];

    if (tid < NC / 4) ((float4*)(out + (size_t)b * NC))[tid] = ov;
    if (tid == 0) out[(size_t)NB * NC + b] = (float)e;

    const int y = y_true[b];
    if (tid == (y >> 2)) {
        float ly = ov.x;
        const int c = y & 3;
        if (c == 1) ly = ov.y;
        else if (c == 2) ly = ov.z;
        else if (c == 3) ly = ov.w;
        atomicAdd(out + (size_t)NB * NC + NB + 0, (s_logZ[e] - ly) * (1.f / NB));
        atomicAdd(out + (size_t)NB * NC + NB + 1, (s_amax[e] == y) ? (1.f / NB) : 0.f);
    }
}

// ------------------------- launch --------------------------------------------
extern "C" void kernel_launch(void* const* d_in, const int* in_sizes, int n_in,
                              void* d_out, int out_size) {
    const float* feats = (const float*)d_in[0];
    const float* Wt    = (const float*)d_in[1];
    const float* bias  = (const float*)d_in[2];
    const int*   y     = (const int*)d_in[3];
    float* out = (float*)d_out;

    cudaFuncSetAttribute(gemm_mma, cudaFuncAttributeMaxDynamicSharedMemorySize, GSMEM);

    conv_all<<<NA_BLK + 32 * 64 * NH, 256>>>(feats, Wt, out);
    gemm_mma<<<dim3(8, 8, NH), 128, GSMEM>>>(bias);
    post_k<<<NB, 256>>>(y, out);
}

// round 12
// speedup vs baseline: 1.1339x; 1.1339x over previous
#include <cuda_runtime.h>
#include <cuda_fp16.h>
#include <math.h>
#include <stdint.h>

#define NH 6
#define NB 512
#define ND 2048
#define NC 1000
#define NP 1024
#define TAU 0.5f

#define BK 32
#define NITER (ND / BK)          // 64
#define STAGES 3
#define STG_BYTES (12 * 1024)    // Ah 4K (64 rows x 64B) | B 8K (32 k-rows x 256B)
#define GSMEM (STAGES * STG_BYTES)

// ------------------------- scratch ------------------------------------------
__device__ __half g_Ah[NH * NB * ND];
__device__ __half g_Bk[NH * ND * NP];   // [h][k][n]  (row-major, n padded)
__device__ float g_logits[NH * NB * NC];

// ------------------------- helpers ------------------------------------------
__device__ __forceinline__ uint32_t smem_u32(const void* p) {
    uint32_t a;
    asm("{ .reg .u64 t; cvta.to.shared.u64 t, %1; cvt.u32.u64 %0, t; }" : "=r"(a) : "l"(p));
    return a;
}
__device__ __forceinline__ void cp16(uint32_t dst, const void* src) {
    asm volatile("cp.async.cg.shared.global [%0], [%1], 16;\n" :: "r"(dst), "l"(src) : "memory");
}
__device__ __forceinline__ void cp_commit() {
    asm volatile("cp.async.commit_group;\n" ::: "memory");
}
template<int N> __device__ __forceinline__ void cp_wait() {
    asm volatile("cp.async.wait_group %0;\n" :: "n"(N) : "memory");
}
// A tiles: 64B rows
__device__ __forceinline__ uint32_t swz_a(uint32_t base, int row, int colb) {
    return base + (uint32_t)(row * 64 + (colb ^ ((row & 6) << 3)));
}
// B tiles: 256B rows (k-major)
__device__ __forceinline__ uint32_t swz_b(uint32_t base, int krow, int colb) {
    return base + (uint32_t)(krow * 256 + (colb ^ ((krow & 7) << 4)));
}
#define LDSM4(r, a) \
    asm volatile("ldmatrix.sync.aligned.m8n8.x4.shared.b16 {%0,%1,%2,%3}, [%4];" \
        : "=r"((r)[0]), "=r"((r)[1]), "=r"((r)[2]), "=r"((r)[3]) : "r"(a))
#define LDSM4T(r, a) \
    asm volatile("ldmatrix.sync.aligned.m8n8.x4.trans.shared.b16 {%0,%1,%2,%3}, [%4];" \
        : "=r"((r)[0]), "=r"((r)[1]), "=r"((r)[2]), "=r"((r)[3]) : "r"(a))
#define MMA16816(c, a, b0, b1) \
    asm volatile("mma.sync.aligned.m16n8k16.row.col.f32.f16.f16.f32 " \
        "{%0,%1,%2,%3}, {%4,%5,%6,%7}, {%8,%9}, {%0,%1,%2,%3};" \
        : "+f"((c)[0]), "+f"((c)[1]), "+f"((c)[2]), "+f"((c)[3]) \
        : "r"((a)[0]), "r"((a)[1]), "r"((a)[2]), "r"((a)[3]), "r"(b0), "r"(b1))

// ------------------------- merged conversion (all elementwise) ---------------
#define NA_BLK (NH * NB * ND / 4 / 256)      // 6144

__global__ __launch_bounds__(256) void conv_all(const float* __restrict__ x,
                                                const float* __restrict__ W,
                                                float* __restrict__ out) {
    const int tid = threadIdx.x;
    if (blockIdx.x < NA_BLK) {
        const int i = blockIdx.x * 256 + tid;
        float4 v = ((const float4*)x)[i];
        __half2* ph = (__half2*)g_Ah;
        ph[2*i]   = __halves2half2(__float2half_rn(v.x), __float2half_rn(v.y));
        ph[2*i+1] = __halves2half2(__float2half_rn(v.z), __float2half_rn(v.w));
        return;
    }
    // B role: one block per (h, k) row: W [h][k][1000] fp32 -> g_Bk [h][k][1024] fp16
    const int bi = blockIdx.x - NA_BLK;          // 0 .. NH*ND-1
    const int h = bi >> 11;
    const int k = bi & (ND - 1);
    if (bi == 0 && tid == 0) {
        out[(size_t)NB * NC + NB + 0] = 0.f;
        out[(size_t)NB * NC + NB + 1] = 0.f;
    }
    const float* wr = W + ((size_t)h * ND + k) * NC;
    const int n = tid * 4;
    float f0 = (n     < NC) ? wr[n]     : 0.f;
    float f1 = (n + 1 < NC) ? wr[n + 1] : 0.f;
    float f2 = (n + 2 < NC) ? wr[n + 2] : 0.f;
    float f3 = (n + 3 < NC) ? wr[n + 3] : 0.f;
    __half2 hv[2];
    hv[0] = __halves2half2(__float2half_rn(f0), __float2half_rn(f1));
    hv[1] = __halves2half2(__float2half_rn(f2), __float2half_rn(f3));
    *(uint2*)(g_Bk + ((size_t)h * ND + k) * NP + n) = *(uint2*)hv;
}

// ------------------------- mma.sync GEMM ------------------------------------
// CTA 64(M)x128(N), 4 warps (warp tile 64x32), BK=32, 3-stage cp.async, occ 4.
// B stored k-major; fragments via ldmatrix.trans.
__global__ void __launch_bounds__(128, 4) gemm_mma(const float* __restrict__ bias) {
    extern __shared__ char sm[];
    const uint32_t sb = smem_u32(sm);
    const int tid = threadIdx.x;
    const int wid = tid >> 5, l = tid & 31;
    const int h  = blockIdx.z;
    const int m0 = blockIdx.y * 64;
    const int n0 = blockIdx.x * 128;

    const __half* Ah = g_Ah + ((size_t)h * NB + m0) * ND;
    const __half* Bk = g_Bk + (size_t)h * ND * NP + n0;   // row k: + k*NP

    // stage: A 256 chunks (64 rows x 4) + B 512 chunks (32 k-rows x 16) = 768
    auto load_stage = [&](int s, int kt) {
        const uint32_t base = sb + (uint32_t)s * STG_BYTES;
        #pragma unroll
        for (int q6 = 0; q6 < 6; q6++) {
            const int q = tid + q6 * 128;
            if (q < 256) {
                const int r  = q >> 2;
                const int ch = q & 3;
                cp16(swz_a(base, r, ch * 16), Ah + (size_t)r * ND + kt + ch * 8);
            } else {
                const int idx = q - 256;
                const int kr  = idx >> 4;          // 0..31
                const int ch  = idx & 15;
                cp16(swz_b(base + 4096u, kr, ch * 16),
                     Bk + (size_t)(kt + kr) * NP + ch * 8);
            }
        }
        cp_commit();
    };

    load_stage(0, 0);
    load_stage(1, BK);

    const int wn = wid * 32;

    float acc[4][4][4];
    #pragma unroll
    for (int a = 0; a < 4; a++)
        #pragma unroll
        for (int b = 0; b < 4; b++)
            #pragma unroll
            for (int c = 0; c < 4; c++) acc[a][b][c] = 0.f;

    const int lrow = l & 15;              // A ldmatrix row
    const int lcb  = (l >> 4) << 4;       // A k-half bytes
    const int bkr  = ((l >> 4) << 3) + (l & 7);   // B trans: k-row within 16
    const int bnb  = ((l >> 3) & 1) * 16;         // B trans: n-chunk bytes

    for (int it = 0; it < NITER; it++) {
        if (it + 2 < NITER) cp_wait<1>(); else cp_wait<0>();
        __syncthreads();

        if (it + 2 < NITER) load_stage((it + 2) % STAGES, (it + 2) * BK);

        const uint32_t base  = sb + (uint32_t)(it % STAGES) * STG_BYTES;
        const uint32_t abase = base;
        const uint32_t bbase = base + 4096u;

        #pragma unroll
        for (int kg = 0; kg < 2; kg++) {
            uint32_t bh_[2][4];
            uint32_t ah_[4][4];
            const int krow = kg * 16 + bkr;
            #pragma unroll
            for (int nt = 0; nt < 2; nt++) {
                const int nb = (wn + nt * 16) * 2 + bnb;
                LDSM4T(bh_[nt], swz_b(bbase, krow, nb));
            }
            const int cb = kg * 32 + lcb;
            #pragma unroll
            for (int mt = 0; mt < 4; mt++) {
                const int row = mt * 16 + lrow;
                LDSM4(ah_[mt], swz_a(abase, row, cb));
            }
            #pragma unroll
            for (int mt = 0; mt < 4; mt++)
                #pragma unroll
                for (int nt = 0; nt < 2; nt++)
                    #pragma unroll
                    for (int hf = 0; hf < 2; hf++)
                        MMA16816(acc[mt][nt * 2 + hf], ah_[mt], bh_[nt][hf], bh_[nt][hf + 2]);
        }
        __syncthreads();
    }

    // epilogue
    float bs0[4], bs1[4];
    #pragma unroll
    for (int n8 = 0; n8 < 4; n8++) {
        const int c0 = n0 + wn + n8 * 8 + (l & 3) * 2;
        bs0[n8] = (c0 < NC)     ? bias[h * NC + c0]     : 0.f;
        bs1[n8] = (c0 + 1 < NC) ? bias[h * NC + c0 + 1] : 0.f;
    }
    #pragma unroll
    for (int mt = 0; mt < 4; mt++) {
        const int r0 = m0 + mt * 16 + (l >> 2);
        #pragma unroll
        for (int n8 = 0; n8 < 4; n8++) {
            const int c0 = n0 + wn + n8 * 8 + (l & 3) * 2;
            if (c0 < NC) {
                float2 v0 = make_float2(acc[mt][n8][0] + bs0[n8], acc[mt][n8][1] + bs1[n8]);
                float2 v1 = make_float2(acc[mt][n8][2] + bs0[n8], acc[mt][n8][3] + bs1[n8]);
                *(float2*)&g_logits[((size_t)h * NB + r0) * NC + c0]     = v0;
                *(float2*)&g_logits[((size_t)h * NB + r0 + 8) * NC + c0] = v1;
            }
        }
    }
}

// ------------------------- fused post-processing -----------------------------
__global__ __launch_bounds__(256) void post_k(const int* __restrict__ y_true,
                                              float* __restrict__ out) {
    const int b = blockIdx.x;
    const int tid = threadIdx.x;
    const int w = tid >> 5, lane = tid & 31;

    __shared__ float swv[8];
    __shared__ int   swi[8];
    __shared__ float sws[8];
    __shared__ float s_conf[NH], s_logZ[NH];
    __shared__ int   s_amax[NH];

    float4 v[NH];
    #pragma unroll
    for (int h = 0; h < NH; h++) {
        v[h] = (tid < NC / 4)
             ? ((const float4*)(g_logits + ((size_t)h * NB + b) * NC))[tid]
             : make_float4(-1e30f, -1e30f, -1e30f, -1e30f);
    }

    #pragma unroll
    for (int h = 0; h < NH; h++) {
        float4 x = v[h];
        float vmax = x.x; int imax = tid * 4;
        if (x.y > vmax) { vmax = x.y; imax = tid * 4 + 1; }
        if (x.z > vmax) { vmax = x.z; imax = tid * 4 + 2; }
        if (x.w > vmax) { vmax = x.w; imax = tid * 4 + 3; }
        #pragma unroll
        for (int off = 16; off > 0; off >>= 1) {
            float ov = __shfl_down_sync(0xffffffffu, vmax, off);
            int   oi = __shfl_down_sync(0xffffffffu, imax, off);
            if (ov > vmax || (ov == vmax && oi < imax)) { vmax = ov; imax = oi; }
        }
        if (lane == 0) { swv[w] = vmax; swi[w] = imax; }
        __syncthreads();
        if (tid < 8) {
            vmax = swv[tid]; imax = swi[tid];
            #pragma unroll
            for (int off = 4; off > 0; off >>= 1) {
                float ov = __shfl_down_sync(0xffu, vmax, off);
                int   oi = __shfl_down_sync(0xffu, imax, off);
                if (ov > vmax || (ov == vmax && oi < imax)) { vmax = ov; imax = oi; }
            }
            if (tid == 0) { swv[0] = vmax; swi[0] = imax; }
        }
        __syncthreads();
        const float m = swv[0];
        const int  am = swi[0];

        float sum = __expf(x.x - m) + __expf(x.y - m) + __expf(x.z - m) + __expf(x.w - m);
        #pragma unroll
        for (int off = 16; off > 0; off >>= 1)
            sum += __shfl_down_sync(0xffffffffu, sum, off);
        if (lane == 0) sws[w] = sum;
        __syncthreads();
        if (tid == 0) {
            float s = 0.f;
            #pragma unroll
            for (int i = 0; i < 8; i++) s += sws[i];
            s_conf[h] = 1.f / s;
            s_logZ[h] = m + logf(s);
            s_amax[h] = am;
        }
        __syncthreads();
    }

    int fh = -1, bh = 0;
    float bc = -1.f;
    #pragma unroll
    for (int hh = 0; hh < NH; hh++) {
        float cv = s_conf[hh];
        if (fh < 0 && cv >= TAU) fh = hh;
        if (cv > bc) { bc = cv; bh = hh; }
    }
    const int e = (fh >= 0) ? fh : bh;

    float4 ov = v[0];
    #pragma unroll
    for (int h = 1; h < NH; h++) if (h == e) ov = v[h];

    if (tid < NC / 4) ((float4*)(out + (size_t)b * NC))[tid] = ov;
    if (tid == 0) out[(size_t)NB * NC + b] = (float)e;

    const int y = y_true[b];
    if (tid == (y >> 2)) {
        float ly = ov.x;
        const int c = y & 3;
        if (c == 1) ly = ov.y;
        else if (c == 2) ly = ov.z;
        else if (c == 3) ly = ov.w;
        atomicAdd(out + (size_t)NB * NC + NB + 0, (s_logZ[e] - ly) * (1.f / NB));
        atomicAdd(out + (size_t)NB * NC + NB + 1, (s_amax[e] == y) ? (1.f / NB) : 0.f);
    }
}

// ------------------------- launch --------------------------------------------
extern "C" void kernel_launch(void* const* d_in, const int* in_sizes, int n_in,
                              void* d_out, int out_size) {
    const float* feats = (const float*)d_in[0];
    const float* Wt    = (const float*)d_in[1];
    const float* bias  = (const float*)d_in[2];
    const int*   y     = (const int*)d_in[3];
    float* out = (float*)d_out;

    cudaFuncSetAttribute(gemm_mma, cudaFuncAttributeMaxDynamicSharedMemorySize, GSMEM);

    conv_all<<<NA_BLK + NH * ND, 256>>>(feats, Wt, out);
    gemm_mma<<<dim3(8, 8, NH), 128, GSMEM>>>(bias);
    post_k<<<NB, 256>>>(y, out);
}

// round 13
// speedup vs baseline: 1.2332x; 1.0876x over previous
#include <cuda_runtime.h>
#include <cuda_fp16.h>
#include <math.h>
#include <stdint.h>

#define NH 6
#define NB 512
#define ND 2048
#define NC 1000
#define NP 1024
#define TAU 0.5f

#define BK 64
#define NITER (ND / BK)          // 32
#define STAGES 3
#define STG_BYTES (24 * 1024)    // Ah 8K (64 rows x 128B) | B 16K (64 k-rows x 256B)
#define GSMEM (STAGES * STG_BYTES)

// ------------------------- scratch ------------------------------------------
__device__ __half g_Ah[NH * NB * ND];
__device__ __half g_Bk[NH * ND * NP];   // [h][k][n]
__device__ float g_logits[NH * NB * NC];

// ------------------------- helpers ------------------------------------------
__device__ __forceinline__ uint32_t smem_u32(const void* p) {
    uint32_t a;
    asm("{ .reg .u64 t; cvta.to.shared.u64 t, %1; cvt.u32.u64 %0, t; }" : "=r"(a) : "l"(p));
    return a;
}
__device__ __forceinline__ void cp16(uint32_t dst, const void* src) {
    asm volatile("cp.async.cg.shared.global [%0], [%1], 16;\n" :: "r"(dst), "l"(src) : "memory");
}
__device__ __forceinline__ void cp_commit() {
    asm volatile("cp.async.commit_group;\n" ::: "memory");
}
template<int N> __device__ __forceinline__ void cp_wait() {
    asm volatile("cp.async.wait_group %0;\n" :: "n"(N) : "memory");
}
// A tiles: 128B rows, full SW128 swizzle
__device__ __forceinline__ uint32_t swz_a(uint32_t base, int row, int colb) {
    return base + (uint32_t)(row * 128 + (colb ^ ((row & 7) << 4)));
}
// B tiles: 256B rows (k-major)
__device__ __forceinline__ uint32_t swz_b(uint32_t base, int krow, int colb) {
    return base + (uint32_t)(krow * 256 + (colb ^ ((krow & 7) << 4)));
}
#define LDSM4(r, a) \
    asm volatile("ldmatrix.sync.aligned.m8n8.x4.shared.b16 {%0,%1,%2,%3}, [%4];" \
        : "=r"((r)[0]), "=r"((r)[1]), "=r"((r)[2]), "=r"((r)[3]) : "r"(a))
#define LDSM4T(r, a) \
    asm volatile("ldmatrix.sync.aligned.m8n8.x4.trans.shared.b16 {%0,%1,%2,%3}, [%4];" \
        : "=r"((r)[0]), "=r"((r)[1]), "=r"((r)[2]), "=r"((r)[3]) : "r"(a))
#define MMA16816(c, a, b0, b1) \
    asm volatile("mma.sync.aligned.m16n8k16.row.col.f32.f16.f16.f32 " \
        "{%0,%1,%2,%3}, {%4,%5,%6,%7}, {%8,%9}, {%0,%1,%2,%3};" \
        : "+f"((c)[0]), "+f"((c)[1]), "+f"((c)[2]), "+f"((c)[3]) \
        : "r"((a)[0]), "r"((a)[1]), "r"((a)[2]), "r"((a)[3]), "r"(b0), "r"(b1))

// ------------------------- merged conversion ---------------------------------
#define NA_BLK2 (NH * NB * ND / 4 / 512)     // 3072 (A blocks: 2 float4/thread)
#define NB_BLK  (NH * ND / 2)                // 6144 (B blocks: 2 k-rows each)

__global__ __launch_bounds__(256) void conv_all(const float* __restrict__ x,
                                                const float* __restrict__ W,
                                                float* __restrict__ out) {
    const int tid = threadIdx.x;
    if (blockIdx.x < NA_BLK2) {
        __half2* ph = (__half2*)g_Ah;
        #pragma unroll
        for (int j = 0; j < 2; j++) {
            const int i = blockIdx.x * 512 + j * 256 + tid;
            float4 v = ((const float4*)x)[i];
            ph[2*i]   = __halves2half2(__float2half_rn(v.x), __float2half_rn(v.y));
            ph[2*i+1] = __halves2half2(__float2half_rn(v.z), __float2half_rn(v.w));
        }
        return;
    }
    // B role: 2 k-rows per block; 128 threads per row, 8 elems (16B out) each
    const int bi = blockIdx.x - NA_BLK2;     // 0 .. NB_BLK-1
    if (bi == 0 && tid == 0) {
        out[(size_t)NB * NC + NB + 0] = 0.f;
        out[(size_t)NB * NC + NB + 1] = 0.f;
    }
    const int row = bi * 2 + (tid >> 7);     // global (h*ND + k)
    const int n = (tid & 127) * 8;
    const float* wr = W + (size_t)row * NC;
    float f[8];
    if (n + 8 <= NC) {
        float4 a = *(const float4*)(wr + n);
        float4 b = *(const float4*)(wr + n + 4);
        f[0]=a.x; f[1]=a.y; f[2]=a.z; f[3]=a.w;
        f[4]=b.x; f[5]=b.y; f[6]=b.z; f[7]=b.w;
    } else {
        #pragma unroll
        for (int j = 0; j < 8; j++) f[j] = (n + j < NC) ? wr[n + j] : 0.f;
    }
    __half2 hv[4];
    #pragma unroll
    for (int j = 0; j < 4; j++)
        hv[j] = __halves2half2(__float2half_rn(f[2*j]), __float2half_rn(f[2*j+1]));
    *(uint4*)(g_Bk + (size_t)row * NP + n) = *(uint4*)hv;
}

// ------------------------- mma.sync GEMM ------------------------------------
// CTA 64(M)x128(N), 4 warps (warp tile 64x32), BK=64, 3-stage cp.async, occ 3.
__global__ void __launch_bounds__(128, 3) gemm_mma(const float* __restrict__ bias) {
    extern __shared__ char sm[];
    const uint32_t sb = smem_u32(sm);
    const int tid = threadIdx.x;
    const int wid = tid >> 5, l = tid & 31;
    const int h  = blockIdx.z;
    const int m0 = blockIdx.y * 64;
    const int n0 = blockIdx.x * 128;

    const __half* Ah = g_Ah + ((size_t)h * NB + m0) * ND;
    const __half* Bk = g_Bk + (size_t)h * ND * NP + n0;

    // stage: A 512 chunks (64 rows x 8) + B 1024 chunks (64 k-rows x 16) = 1536
    auto load_stage = [&](int s, int kt) {
        const uint32_t base = sb + (uint32_t)s * STG_BYTES;
        #pragma unroll
        for (int q12 = 0; q12 < 12; q12++) {
            const int q = tid + q12 * 128;
            if (q < 512) {
                const int r  = q >> 3;
                const int ch = q & 7;
                cp16(swz_a(base, r, ch * 16), Ah + (size_t)r * ND + kt + ch * 8);
            } else {
                const int idx = q - 512;
                const int kr  = idx >> 4;          // 0..63
                const int ch  = idx & 15;
                cp16(swz_b(base + 8192u, kr, ch * 16),
                     Bk + (size_t)(kt + kr) * NP + ch * 8);
            }
        }
        cp_commit();
    };

    load_stage(0, 0);
    load_stage(1, BK);

    const int wn = wid * 32;

    float acc[4][4][4];
    #pragma unroll
    for (int a = 0; a < 4; a++)
        #pragma unroll
        for (int b = 0; b < 4; b++)
            #pragma unroll
            for (int c = 0; c < 4; c++) acc[a][b][c] = 0.f;

    const int lrow = l & 15;
    const int lcb  = (l >> 4) << 4;
    const int bkr  = ((l >> 4) << 3) + (l & 7);
    const int bnb  = ((l >> 3) & 1) * 16;

    for (int it = 0; it < NITER; it++) {
        if (it + 2 < NITER) cp_wait<1>(); else cp_wait<0>();
        __syncthreads();

        if (it + 2 < NITER) load_stage((it + 2) % STAGES, (it + 2) * BK);

        const uint32_t base  = sb + (uint32_t)(it % STAGES) * STG_BYTES;
        const uint32_t abase = base;
        const uint32_t bbase = base + 8192u;

        #pragma unroll
        for (int kg = 0; kg < 4; kg++) {
            uint32_t bh_[2][4];
            uint32_t ah_[4][4];
            const int krow = kg * 16 + bkr;
            #pragma unroll
            for (int nt = 0; nt < 2; nt++) {
                const int nb = (wn + nt * 16) * 2 + bnb;
                LDSM4T(bh_[nt], swz_b(bbase, krow, nb));
            }
            const int cb = kg * 32 + lcb;
            #pragma unroll
            for (int mt = 0; mt < 4; mt++) {
                const int row = mt * 16 + lrow;
                LDSM4(ah_[mt], swz_a(abase, row, cb));
            }
            #pragma unroll
            for (int mt = 0; mt < 4; mt++)
                #pragma unroll
                for (int nt = 0; nt < 2; nt++)
                    #pragma unroll
                    for (int hf = 0; hf < 2; hf++)
                        MMA16816(acc[mt][nt * 2 + hf], ah_[mt], bh_[nt][hf], bh_[nt][hf + 2]);
        }
        __syncthreads();
    }

    // epilogue
    float bs0[4], bs1[4];
    #pragma unroll
    for (int n8 = 0; n8 < 4; n8++) {
        const int c0 = n0 + wn + n8 * 8 + (l & 3) * 2;
        bs0[n8] = (c0 < NC)     ? bias[h * NC + c0]     : 0.f;
        bs1[n8] = (c0 + 1 < NC) ? bias[h * NC + c0 + 1] : 0.f;
    }
    #pragma unroll
    for (int mt = 0; mt < 4; mt++) {
        const int r0 = m0 + mt * 16 + (l >> 2);
        #pragma unroll
        for (int n8 = 0; n8 < 4; n8++) {
            const int c0 = n0 + wn + n8 * 8 + (l & 3) * 2;
            if (c0 < NC) {
                float2 v0 = make_float2(acc[mt][n8][0] + bs0[n8], acc[mt][n8][1] + bs1[n8]);
                float2 v1 = make_float2(acc[mt][n8][2] + bs0[n8], acc[mt][n8][3] + bs1[n8]);
                *(float2*)&g_logits[((size_t)h * NB + r0) * NC + c0]     = v0;
                *(float2*)&g_logits[((size_t)h * NB + r0 + 8) * NC + c0] = v1;
            }
        }
    }
}

// ------------------------- fused post-processing -----------------------------
__global__ __launch_bounds__(256) void post_k(const int* __restrict__ y_true,
                                              float* __restrict__ out) {
    const int b = blockIdx.x;
    const int tid = threadIdx.x;
    const int w = tid >> 5, lane = tid & 31;

    __shared__ float swv[8];
    __shared__ int   swi[8];
    __shared__ float sws[8];
    __shared__ float s_conf[NH], s_logZ[NH];
    __shared__ int   s_amax[NH];

    float4 v[NH];
    #pragma unroll
    for (int h = 0; h < NH; h++) {
        v[h] = (tid < NC / 4)
             ? ((const float4*)(g_logits + ((size_t)h * NB + b) * NC))[tid]
             : make_float4(-1e30f, -1e30f, -1e30f, -1e30f);
    }

    #pragma unroll
    for (int h = 0; h < NH; h++) {
        float4 x = v[h];
        float vmax = x.x; int imax = tid * 4;
        if (x.y > vmax) { vmax = x.y; imax = tid * 4 + 1; }
        if (x.z > vmax) { vmax = x.z; imax = tid * 4 + 2; }
        if (x.w > vmax) { vmax = x.w; imax = tid * 4 + 3; }
        #pragma unroll
        for (int off = 16; off > 0; off >>= 1) {
            float ov = __shfl_down_sync(0xffffffffu, vmax, off);
            int   oi = __shfl_down_sync(0xffffffffu, imax, off);
            if (ov > vmax || (ov == vmax && oi < imax)) { vmax = ov; imax = oi; }
        }
        if (lane == 0) { swv[w] = vmax; swi[w] = imax; }
        __syncthreads();
        if (tid < 8) {
            vmax = swv[tid]; imax = swi[tid];
            #pragma unroll
            for (int off = 4; off > 0; off >>= 1) {
                float ov = __shfl_down_sync(0xffu, vmax, off);
                int   oi = __shfl_down_sync(0xffu, imax, off);
                if (ov > vmax || (ov == vmax && oi < imax)) { vmax = ov; imax = oi; }
            }
            if (tid == 0) { swv[0] = vmax; swi[0] = imax; }
        }
        __syncthreads();
        const float m = swv[0];
        const int  am = swi[0];

        float sum = __expf(x.x - m) + __expf(x.y - m) + __expf(x.z - m) + __expf(x.w - m);
        #pragma unroll
        for (int off = 16; off > 0; off >>= 1)
            sum += __shfl_down_sync(0xffffffffu, sum, off);
        if (lane == 0) sws[w] = sum;
        __syncthreads();
        if (tid == 0) {
            float s = 0.f;
            #pragma unroll
            for (int i = 0; i < 8; i++) s += sws[i];
            s_conf[h] = 1.f / s;
            s_logZ[h] = m + logf(s);
            s_amax[h] = am;
        }
        __syncthreads();
    }

    int fh = -1, bh = 0;
    float bc = -1.f;
    #pragma unroll
    for (int hh = 0; hh < NH; hh++) {
        float cv = s_conf[hh];
        if (fh < 0 && cv >= TAU) fh = hh;
        if (cv > bc) { bc = cv; bh = hh; }
    }
    const int e = (fh >= 0) ? fh : bh;

    float4 ov = v[0];
    #pragma unroll
    for (int h = 1; h < NH; h++) if (h == e) ov = v[h];

    if (tid < NC / 4) ((float4*)(out + (size_t)b * NC))[tid] = ov;
    if (tid == 0) out[(size_t)NB * NC + b] = (float)e;

    const int y = y_true[b];
    if (tid == (y >> 2)) {
        float ly = ov.x;
        const int c = y & 3;
        if (c == 1) ly = ov.y;
        else if (c == 2) ly = ov.z;
        else if (c == 3) ly = ov.w;
        atomicAdd(out + (size_t)NB * NC + NB + 0, (s_logZ[e] - ly) * (1.f / NB));
        atomicAdd(out + (size_t)NB * NC + NB + 1, (s_amax[e] == y) ? (1.f / NB) : 0.f);
    }
}

// ------------------------- launch --------------------------------------------
extern "C" void kernel_launch(void* const* d_in, const int* in_sizes, int n_in,
                              void* d_out, int out_size) {
    const float* feats = (const float*)d_in[0];
    const float* Wt    = (const float*)d_in[1];
    const float* bias  = (const float*)d_in[2];
    const int*   y     = (const int*)d_in[3];
    float* out = (float*)d_out;

    cudaFuncSetAttribute(gemm_mma, cudaFuncAttributeMaxDynamicSharedMemorySize, GSMEM);

    conv_all<<<NA_BLK2 + NB_BLK, 256>>>(feats, Wt, out);
    gemm_mma<<<dim3(8, 8, NH), 128, GSMEM>>>(bias);
    post_k<<<NB, 256>>>(y, out);
}

// round 14
// speedup vs baseline: 1.2551x; 1.0177x over previous
#include <cuda_runtime.h>
#include <cuda_fp16.h>
#include <math.h>
#include <stdint.h>

#define NH 6
#define NB 512
#define ND 2048
#define NC 1000
#define NP 1024
#define TAU 0.5f

#define BK 64
#define NITER (ND / BK)          // 32
#define STAGES 3
#define STG_BYTES (24 * 1024)    // Ah 8K (64 rows x 128B) | B 16K (64 k-rows x 256B)
#define GSMEM (STAGES * STG_BYTES)

// ------------------------- scratch ------------------------------------------
__device__ __half g_Ah[NH * NB * ND];
__device__ __half g_Bk[NH * ND * NP];   // [h][k][n]
__device__ float g_logits[NH * NB * NC];

// ------------------------- helpers ------------------------------------------
__device__ __forceinline__ uint32_t smem_u32(const void* p) {
    uint32_t a;
    asm("{ .reg .u64 t; cvta.to.shared.u64 t, %1; cvt.u32.u64 %0, t; }" : "=r"(a) : "l"(p));
    return a;
}
__device__ __forceinline__ void cp16(uint32_t dst, const void* src) {
    asm volatile("cp.async.cg.shared.global [%0], [%1], 16;\n" :: "r"(dst), "l"(src) : "memory");
}
__device__ __forceinline__ void cp_commit() {
    asm volatile("cp.async.commit_group;\n" ::: "memory");
}
template<int N> __device__ __forceinline__ void cp_wait() {
    asm volatile("cp.async.wait_group %0;\n" :: "n"(N) : "memory");
}
__device__ __forceinline__ uint32_t swz_a(uint32_t base, int row, int colb) {
    return base + (uint32_t)(row * 128 + (colb ^ ((row & 7) << 4)));
}
__device__ __forceinline__ uint32_t swz_b(uint32_t base, int krow, int colb) {
    return base + (uint32_t)(krow * 256 + (colb ^ ((krow & 7) << 4)));
}
#define LDSM4(r, a) \
    asm volatile("ldmatrix.sync.aligned.m8n8.x4.shared.b16 {%0,%1,%2,%3}, [%4];" \
        : "=r"((r)[0]), "=r"((r)[1]), "=r"((r)[2]), "=r"((r)[3]) : "r"(a))
#define LDSM4T(r, a) \
    asm volatile("ldmatrix.sync.aligned.m8n8.x4.trans.shared.b16 {%0,%1,%2,%3}, [%4];" \
        : "=r"((r)[0]), "=r"((r)[1]), "=r"((r)[2]), "=r"((r)[3]) : "r"(a))
#define MMA16816(c, a, b0, b1) \
    asm volatile("mma.sync.aligned.m16n8k16.row.col.f32.f16.f16.f32 " \
        "{%0,%1,%2,%3}, {%4,%5,%6,%7}, {%8,%9}, {%0,%1,%2,%3};" \
        : "+f"((c)[0]), "+f"((c)[1]), "+f"((c)[2]), "+f"((c)[3]) \
        : "r"((a)[0]), "r"((a)[1]), "r"((a)[2]), "r"((a)[3]), "r"(b0), "r"(b1))

// ------------------------- merged conversion ---------------------------------
#define NA_BLK2 (NH * NB * ND / 4 / 512)     // 3072
#define NB_BLK  (NH * ND / 2)                // 6144

__global__ __launch_bounds__(256) void conv_all(const float* __restrict__ x,
                                                const float* __restrict__ W,
                                                float* __restrict__ out) {
    const int tid = threadIdx.x;
    if (blockIdx.x < NA_BLK2) {
        __half2* ph = (__half2*)g_Ah;
        #pragma unroll
        for (int j = 0; j < 2; j++) {
            const int i = blockIdx.x * 512 + j * 256 + tid;
            float4 v = ((const float4*)x)[i];
            ph[2*i]   = __halves2half2(__float2half_rn(v.x), __float2half_rn(v.y));
            ph[2*i+1] = __halves2half2(__float2half_rn(v.z), __float2half_rn(v.w));
        }
        return;
    }
    const int bi = blockIdx.x - NA_BLK2;
    if (bi == 0 && tid == 0) {
        out[(size_t)NB * NC + NB + 0] = 0.f;
        out[(size_t)NB * NC + NB + 1] = 0.f;
    }
    const int row = bi * 2 + (tid >> 7);
    const int n = (tid & 127) * 8;
    const float* wr = W + (size_t)row * NC;
    float f[8];
    if (n + 8 <= NC) {
        float4 a = *(const float4*)(wr + n);
        float4 b = *(const float4*)(wr + n + 4);
        f[0]=a.x; f[1]=a.y; f[2]=a.z; f[3]=a.w;
        f[4]=b.x; f[5]=b.y; f[6]=b.z; f[7]=b.w;
    } else {
        #pragma unroll
        for (int j = 0; j < 8; j++) f[j] = (n + j < NC) ? wr[n + j] : 0.f;
    }
    __half2 hv[4];
    #pragma unroll
    for (int j = 0; j < 4; j++)
        hv[j] = __halves2half2(__float2half_rn(f[2*j]), __float2half_rn(f[2*j+1]));
    *(uint4*)(g_Bk + (size_t)row * NP + n) = *(uint4*)hv;
}

// ------------------------- mma.sync GEMM (unchanged from R13) ----------------
__global__ void __launch_bounds__(128, 3) gemm_mma(const float* __restrict__ bias) {
    extern __shared__ char sm[];
    const uint32_t sb = smem_u32(sm);
    const int tid = threadIdx.x;
    const int wid = tid >> 5, l = tid & 31;
    const int h  = blockIdx.z;
    const int m0 = blockIdx.y * 64;
    const int n0 = blockIdx.x * 128;

    const __half* Ah = g_Ah + ((size_t)h * NB + m0) * ND;
    const __half* Bk = g_Bk + (size_t)h * ND * NP + n0;

    auto load_stage = [&](int s, int kt) {
        const uint32_t base = sb + (uint32_t)s * STG_BYTES;
        #pragma unroll
        for (int q12 = 0; q12 < 12; q12++) {
            const int q = tid + q12 * 128;
            if (q < 512) {
                const int r  = q >> 3;
                const int ch = q & 7;
                cp16(swz_a(base, r, ch * 16), Ah + (size_t)r * ND + kt + ch * 8);
            } else {
                const int idx = q - 512;
                const int kr  = idx >> 4;
                const int ch  = idx & 15;
                cp16(swz_b(base + 8192u, kr, ch * 16),
                     Bk + (size_t)(kt + kr) * NP + ch * 8);
            }
        }
        cp_commit();
    };

    load_stage(0, 0);
    load_stage(1, BK);

    const int wn = wid * 32;

    float acc[4][4][4];
    #pragma unroll
    for (int a = 0; a < 4; a++)
        #pragma unroll
        for (int b = 0; b < 4; b++)
            #pragma unroll
            for (int c = 0; c < 4; c++) acc[a][b][c] = 0.f;

    const int lrow = l & 15;
    const int lcb  = (l >> 4) << 4;
    const int bkr  = ((l >> 4) << 3) + (l & 7);
    const int bnb  = ((l >> 3) & 1) * 16;

    for (int it = 0; it < NITER; it++) {
        if (it + 2 < NITER) cp_wait<1>(); else cp_wait<0>();
        __syncthreads();

        if (it + 2 < NITER) load_stage((it + 2) % STAGES, (it + 2) * BK);

        const uint32_t base  = sb + (uint32_t)(it % STAGES) * STG_BYTES;
        const uint32_t abase = base;
        const uint32_t bbase = base + 8192u;

        #pragma unroll
        for (int kg = 0; kg < 4; kg++) {
            uint32_t bh_[2][4];
            uint32_t ah_[4][4];
            const int krow = kg * 16 + bkr;
            #pragma unroll
            for (int nt = 0; nt < 2; nt++) {
                const int nb = (wn + nt * 16) * 2 + bnb;
                LDSM4T(bh_[nt], swz_b(bbase, krow, nb));
            }
            const int cb = kg * 32 + lcb;
            #pragma unroll
            for (int mt = 0; mt < 4; mt++) {
                const int row = mt * 16 + lrow;
                LDSM4(ah_[mt], swz_a(abase, row, cb));
            }
            #pragma unroll
            for (int mt = 0; mt < 4; mt++)
                #pragma unroll
                for (int nt = 0; nt < 2; nt++)
                    #pragma unroll
                    for (int hf = 0; hf < 2; hf++)
                        MMA16816(acc[mt][nt * 2 + hf], ah_[mt], bh_[nt][hf], bh_[nt][hf + 2]);
        }
        __syncthreads();
    }

    float bs0[4], bs1[4];
    #pragma unroll
    for (int n8 = 0; n8 < 4; n8++) {
        const int c0 = n0 + wn + n8 * 8 + (l & 3) * 2;
        bs0[n8] = (c0 < NC)     ? bias[h * NC + c0]     : 0.f;
        bs1[n8] = (c0 + 1 < NC) ? bias[h * NC + c0 + 1] : 0.f;
    }
    #pragma unroll
    for (int mt = 0; mt < 4; mt++) {
        const int r0 = m0 + mt * 16 + (l >> 2);
        #pragma unroll
        for (int n8 = 0; n8 < 4; n8++) {
            const int c0 = n0 + wn + n8 * 8 + (l & 3) * 2;
            if (c0 < NC) {
                float2 v0 = make_float2(acc[mt][n8][0] + bs0[n8], acc[mt][n8][1] + bs1[n8]);
                float2 v1 = make_float2(acc[mt][n8][2] + bs0[n8], acc[mt][n8][3] + bs1[n8]);
                *(float2*)&g_logits[((size_t)h * NB + r0) * NC + c0]     = v0;
                *(float2*)&g_logits[((size_t)h * NB + r0 + 8) * NC + c0] = v1;
            }
        }
    }
}

// ------------------------- fused post-processing (warp-per-head) -------------
// 192 threads = 6 warps; warp w owns head w. One barrier per block.
__global__ __launch_bounds__(192) void post_k(const int* __restrict__ y_true,
                                              float* __restrict__ out) {
    const int b = blockIdx.x;
    const int w = threadIdx.x >> 5;       // head
    const int lane = threadIdx.x & 31;

    __shared__ float s_conf[NH], s_logZ[NH];
    __shared__ int   s_amax[NH];

    const float4* row = (const float4*)(g_logits + ((size_t)w * NB + b) * NC);
    float4 v[8];
    #pragma unroll
    for (int i = 0; i < 8; i++) {
        const int j = i * 32 + lane;
        v[i] = (j < NC / 4) ? row[j] : make_float4(-1e30f, -1e30f, -1e30f, -1e30f);
    }

    // max/argmax (first occurrence) — indices increase across i, then component
    float vmax = -1e30f; int imax = 0;
    #pragma unroll
    for (int i = 0; i < 8; i++) {
        const int j = i * 32 + lane;
        const float* p = (const float*)&v[i];
        #pragma unroll
        for (int c = 0; c < 4; c++)
            if (p[c] > vmax) { vmax = p[c]; imax = j * 4 + c; }
    }
    #pragma unroll
    for (int off = 16; off > 0; off >>= 1) {
        float ov = __shfl_down_sync(0xffffffffu, vmax, off);
        int   oi = __shfl_down_sync(0xffffffffu, imax, off);
        if (ov > vmax || (ov == vmax && oi < imax)) { vmax = ov; imax = oi; }
    }
    vmax = __shfl_sync(0xffffffffu, vmax, 0);
    imax = __shfl_sync(0xffffffffu, imax, 0);

    float sum = 0.f;
    #pragma unroll
    for (int i = 0; i < 8; i++) {
        const int j = i * 32 + lane;
        if (j < NC / 4)
            sum += __expf(v[i].x - vmax) + __expf(v[i].y - vmax)
                 + __expf(v[i].z - vmax) + __expf(v[i].w - vmax);
    }
    #pragma unroll
    for (int off = 16; off > 0; off >>= 1)
        sum += __shfl_down_sync(0xffffffffu, sum, off);

    if (lane == 0) {
        s_conf[w] = 1.f / sum;
        s_logZ[w] = vmax + logf(sum);
        s_amax[w] = imax;
    }
    __syncthreads();

    int fh = -1, bh = 0;
    float bc = -1.f;
    #pragma unroll
    for (int hh = 0; hh < NH; hh++) {
        const float cv = s_conf[hh];
        if (fh < 0 && cv >= TAU) fh = hh;
        if (cv > bc) { bc = cv; bh = hh; }
    }
    const int e = (fh >= 0) ? fh : bh;

    if (w == e) {
        float4* dst = (float4*)(out + (size_t)b * NC);
        const int y = y_true[b];
        #pragma unroll
        for (int i = 0; i < 8; i++) {
            const int j = i * 32 + lane;
            if (j < NC / 4) dst[j] = v[i];
        }
        #pragma unroll
        for (int i = 0; i < 8; i++) {
            const int j = i * 32 + lane;
            if (j == (y >> 2)) {
                const float* p = (const float*)&v[i];
                const float ly = p[y & 3];
                atomicAdd(out + (size_t)NB * NC + NB + 0, (s_logZ[e] - ly) * (1.f / NB));
                atomicAdd(out + (size_t)NB * NC + NB + 1, (s_amax[e] == y) ? (1.f / NB) : 0.f);
            }
        }
        if (lane == 0) out[(size_t)NB * NC + b] = (float)e;
    }
}

// ------------------------- launch --------------------------------------------
extern "C" void kernel_launch(void* const* d_in, const int* in_sizes, int n_in,
                              void* d_out, int out_size) {
    const float* feats = (const float*)d_in[0];
    const float* Wt    = (const float*)d_in[1];
    const float* bias  = (const float*)d_in[2];
    const int*   y     = (const int*)d_in[3];
    float* out = (float*)d_out;

    cudaFuncSetAttribute(gemm_mma, cudaFuncAttributeMaxDynamicSharedMemorySize, GSMEM);

    conv_all<<<NA_BLK2 + NB_BLK, 256>>>(feats, Wt, out);
    gemm_mma<<<dim3(8, 8, NH), 128, GSMEM>>>(bias);
    post_k<<<NB, 192>>>(y, out);
}